// round 13
// baseline (speedup 1.0000x reference)
#include <cuda_runtime.h>
#include <math_constants.h>
#include <cstdint>

#define NB    4
#define SQ    2048
#define UU    1024
#define DKD   64
#define NEGC  1.0e9f
#define SCL   0.125f   // 1/sqrt(64)
#define NSPL  4        // key splits (512 keys each)

// ---------------- scratch (no allocation allowed) ----------------
// g_Qp / g_Kp: [8192][64] tf32-rounded, k-dim PERMUTED within 8-groups:
//   group positions hold {k0,k4,k1,k5,k2,k6,k3,k7}
// g_Vt: [B][64(d)][2048(s)] tf32-rounded, transposed
// g_Wp: [3][64][1024] tf32-rounded + permuted weights
__device__ float g_Qp[(size_t)NB * SQ * DKD];
__device__ float g_Kp[(size_t)NB * SQ * DKD];
__device__ float g_Vt[(size_t)NB * DKD * SQ];
__device__ float g_Wp[(size_t)3 * DKD * UU];
// split-K partials
__device__ float g_Po[(size_t)NSPL * NB * SQ * DKD];
__device__ float g_Pm[(size_t)NSPL * NB * SQ];
__device__ float g_Pl[(size_t)NSPL * NB * SQ];

// ---------------- helpers ----------------
__device__ __forceinline__ float tf32f(float x) {
    uint32_t u;
    asm("cvt.rna.tf32.f32 %0, %1;" : "=r"(u) : "f"(x));
    return __uint_as_float(u);
}
__device__ __forceinline__ uint32_t tf32u(float x) {
    uint32_t u;
    asm("cvt.rna.tf32.f32 %0, %1;" : "=r"(u) : "f"(x));
    return u;
}
__device__ __forceinline__ void mma8(float* c,
                                     uint32_t a0, uint32_t a1, uint32_t a2, uint32_t a3,
                                     uint32_t b0, uint32_t b1) {
    asm volatile(
        "mma.sync.aligned.m16n8k8.row.col.f32.tf32.tf32.f32 "
        "{%0,%1,%2,%3}, {%4,%5,%6,%7}, {%8,%9}, {%0,%1,%2,%3};\n"
        : "+f"(c[0]), "+f"(c[1]), "+f"(c[2]), "+f"(c[3])
        : "r"(a0), "r"(a1), "r"(a2), "r"(a3), "r"(b0), "r"(b1));
}
__device__ __forceinline__ uint32_t smem_u32(const void* p) {
    uint32_t a;
    asm("{ .reg .u64 t; cvta.to.shared.u64 t, %1; cvt.u32.u64 %0, t; }" : "=r"(a) : "l"(p));
    return a;
}
#define CP16(dst, src) \
    asm volatile("cp.async.cg.shared.global [%0], [%1], 16;\n" :: "r"(dst), "l"(src))
#define CPCOMMIT() asm volatile("cp.async.commit_group;\n" ::: "memory")
#define CPWAIT(n)  asm volatile("cp.async.wait_group %0;\n" :: "n"(n) : "memory")

// =======================================================================
// W prep: tf32-round + k-permute all three weight matrices into g_Wp.
// =======================================================================
__global__ __launch_bounds__(256) void wprep(
    const float* __restrict__ Wq, const float* __restrict__ Wk, const float* __restrict__ Wv)
{
    int gid = blockIdx.x * 256 + threadIdx.x;   // 0..24575
    int which = gid >> 13;
    int rem = gid & 8191;
    const float* W = (which == 0) ? Wq : (which == 1) ? Wk : Wv;
    const float* src = W + (size_t)rem * 8;
    float4 lo = *(const float4*)(src);
    float4 hi = *(const float4*)(src + 4);
    float* dst = g_Wp + (size_t)which * (DKD * UU) + (size_t)rem * 8;
    *(uint4*)(dst)     = make_uint4(tf32u(lo.x), tf32u(hi.x), tf32u(lo.y), tf32u(hi.y));
    *(uint4*)(dst + 4) = make_uint4(tf32u(lo.z), tf32u(hi.z), tf32u(lo.w), tf32u(hi.w));
}

// =======================================================================
// Projection GEMM: cp.async 3-stage pipeline, k-steps of 32.
// CTA: 64 rows x 64 cols, 128 threads (4 warps x 16 rows). grid (128, 3).
// 3 stages (58.4 KB) -> 3 CTAs/SM -> single wave. (round-12 proven)
// =======================================================================
#define PXPIT 36
#define PWPIT 40
#define PWOFF (64 * PXPIT)                       // 2304
#define PST   (64 * PXPIT + 64 * PWPIT)          // 4864 floats / stage
#define PSTAGES 3
#define PROJ_SMEM_FLOATS (PSTAGES * PST)         // 14592 floats = 58368 B

__global__ __launch_bounds__(128, 3) void proj_tc(
    const float* __restrict__ Qx, const float* __restrict__ bq,
    const float* __restrict__ Kx, const float* __restrict__ bk,
    const float* __restrict__ Vx, const float* __restrict__ bv)
{
    extern __shared__ float sm[];
    const uint32_t sb = smem_u32(sm);

    const int which = blockIdx.y;
    const float* X    = (which == 0) ? Qx : (which == 1) ? Kx : Vx;
    const float* bias = (which == 0) ? bq : (which == 1) ? bk : bv;
    const float* Wp   = g_Wp + (size_t)which * (DKD * UU);

    const int tid = threadIdx.x;
    const int w   = tid >> 5;
    const int lane = tid & 31;
    const int g = lane >> 2;
    const int t = lane & 3;
    const int m0 = blockIdx.x * 64;

    auto issue = [&](int s) {
        const int k0 = s * 32;
        const uint32_t bs = sb + (uint32_t)((s % PSTAGES) * PST) * 4;
        #pragma unroll
        for (int i = 0; i < 4; i++) {
            int idx = tid + i * 128;
            int r = idx >> 3, seg = idx & 7;
            CP16(bs + (uint32_t)(r * PXPIT + seg * 4) * 4,
                 X + (size_t)(m0 + r) * UU + k0 + seg * 4);
        }
        #pragma unroll
        for (int i = 0; i < 4; i++) {
            int idx = tid + i * 128;
            int r = idx >> 3, seg = idx & 7;
            CP16(bs + (uint32_t)(PWOFF + r * PWPIT + seg * 4) * 4,
                 Wp + (size_t)r * UU + k0 + seg * 4);
        }
        CPCOMMIT();
    };

    issue(0); issue(1);

    float acc[8][4] = {};

    for (int kc = 0; kc < 32; kc++) {
        if (kc + 2 < 32) { issue(kc + 2); CPWAIT(2); }
        else             { CPWAIT(0); }
        __syncthreads();

        const float* bX = sm + (kc % PSTAGES) * PST;
        const float* bW = bX + PWOFF;
        const float* xr0 = &bX[(w * 16 + g) * PXPIT + t];
        const float* xr1 = &bX[(w * 16 + 8 + g) * PXPIT + t];

        #pragma unroll
        for (int ks = 0; ks < 4; ks++) {
            const int cb = ks * 8;
            uint32_t a0 = tf32u(xr0[cb]);
            uint32_t a1 = tf32u(xr1[cb]);
            uint32_t a2 = tf32u(xr0[cb + 4]);
            uint32_t a3 = tf32u(xr1[cb + 4]);
            #pragma unroll
            for (int nb = 0; nb < 8; nb++) {
                uint2 b = *(const uint2*)&bW[(nb * 8 + g) * PWPIT + cb + 2 * t];
                mma8(acc[nb], a0, a1, a2, a3, b.x, b.y);
            }
        }
        __syncthreads();
    }

    // epilogue
    const int lr0 = w * 16 + g, lr1 = lr0 + 8;
    const int t2 = 2 * t;
    const int pA = (t2 < 4) ? 2 * t2 : 2 * (t2 - 4) + 1;
    const int pB = (t2 + 1 < 4) ? 2 * (t2 + 1) : 2 * (t2 - 3) + 1;

    if (which < 2) {
        float* dst = (which == 0) ? g_Qp : g_Kp;
        #pragma unroll
        for (int nb = 0; nb < 8; nb++) {
            float b0 = bias[nb * 8 + t2], b1 = bias[nb * 8 + t2 + 1];
            dst[(size_t)(m0 + lr0) * 64 + nb * 8 + pA] = tf32f(acc[nb][0] + b0);
            dst[(size_t)(m0 + lr0) * 64 + nb * 8 + pB] = tf32f(acc[nb][1] + b1);
            dst[(size_t)(m0 + lr1) * 64 + nb * 8 + pA] = tf32f(acc[nb][2] + b0);
            dst[(size_t)(m0 + lr1) * 64 + nb * 8 + pB] = tf32f(acc[nb][3] + b1);
        }
    } else {
        // V: transpose through smem -> g_Vt[b][d][s]
        float* ob = sm;   // [64][68], fits in stage region
        #pragma unroll
        for (int nb = 0; nb < 8; nb++) {
            float b0 = bias[nb * 8 + t2], b1 = bias[nb * 8 + t2 + 1];
            ob[lr0 * 68 + nb * 8 + t2]     = tf32f(acc[nb][0] + b0);
            ob[lr0 * 68 + nb * 8 + t2 + 1] = tf32f(acc[nb][1] + b1);
            ob[lr1 * 68 + nb * 8 + t2]     = tf32f(acc[nb][2] + b0);
            ob[lr1 * 68 + nb * 8 + t2 + 1] = tf32f(acc[nb][3] + b1);
        }
        __syncthreads();
        const int bidx = m0 >> 11;
        const int sbase = m0 & 2047;
        #pragma unroll
        for (int i = 0; i < 8; i++) {
            int idx = tid + i * 128;       // 64 d * 16 s-groups
            int d = idx >> 4, mg = idx & 15;
            float4 v;
            v.x = ob[(mg * 4 + 0) * 68 + d];
            v.y = ob[(mg * 4 + 1) * 68 + d];
            v.z = ob[(mg * 4 + 2) * 68 + d];
            v.w = ob[(mg * 4 + 3) * 68 + d];
            *(float4*)(g_Vt + ((size_t)(bidx * 64 + d)) * 2048 + sbase + mg * 4) = v;
        }
    }
}

// =======================================================================
// Flash attention, split-K=4: CTA = 4 warps x 16 full query rows,
// 512 keys/split, 4 tiles of 128. grid (32, 4, 4) = 512 CTAs.
// Q fragments loaded DIRECTLY from gmem (permuted layout) -> no Q smem,
// 71.7 KB/CTA -> 3 CTAs/SM resident.
// =======================================================================
#define KPITCH 72
#define VPITCH 136
#define A_KS   0
#define A_VT   (128 * KPITCH)                      // 9216
#define ATT_SMEM_FLOATS (A_VT + 64 * VPITCH)       // 17920 floats = 71680 B

__global__ __launch_bounds__(128, 3) void attn_tc(
    const int* __restrict__ mask)
{
    extern __shared__ float sm[];
    const int tid = threadIdx.x;
    const int w = tid >> 5;
    const int lane = tid & 31;
    const int g = lane >> 2;
    const int t = lane & 3;
    const int qt = blockIdx.x;
    const int sp = blockIdx.y;
    const int bb = blockIdx.z;
    const int q0 = qt * 64;
    const int kbase = sp * (SQ / NSPL);

    // Q fragments straight from gmem (layout already tf32 + permuted)
    uint2 qa0[8], qa1[8];
    {
        const float* qr0 = g_Qp + ((size_t)(bb * SQ + q0 + w * 16 + g)) * 64 + 2 * t;
        const float* qr1 = qr0 + 8 * 64;
        #pragma unroll
        for (int ks = 0; ks < 8; ks++) {
            qa0[ks] = *(const uint2*)(qr0 + ks * 8);
            qa1[ks] = *(const uint2*)(qr1 + ks * 8);
        }
    }

    float m0r = -CUDART_INF_F, m1r = -CUDART_INF_F;
    float l0r = 0.f, l1r = 0.f;
    float o[8][4] = {};

    const int row0 = q0 + w * 16 + g, row1 = row0 + 8;
    const int* mk0 = mask + ((size_t)(bb * SQ + row0)) * SQ + kbase;
    const int* mk1 = mask + ((size_t)(bb * SQ + row1)) * SQ + kbase;
    const float* Kg = g_Kp + ((size_t)(bb * SQ + kbase)) * 64;
    const float* Vg = g_Vt + ((size_t)bb * 64) * 2048 + kbase;

    for (int tile = 0; tile < (SQ / NSPL) / 128; tile++) {
        const int j0 = tile * 128;

        __syncthreads();
        // stage K tile (straight copy, perm layout)
        #pragma unroll
        for (int i = 0; i < 16; i++) {
            int idx = tid + i * 128;
            int r = idx >> 4, c4 = idx & 15;
            *(float4*)&sm[A_KS + r * KPITCH + c4 * 4] =
                *(const float4*)(Kg + (size_t)(j0 + r) * 64 + c4 * 4);
        }
        // stage V^T tile
        #pragma unroll
        for (int i = 0; i < 16; i++) {
            int idx = tid + i * 128;
            int d = idx >> 5, c4 = idx & 31;
            *(float4*)&sm[A_VT + d * VPITCH + c4 * 4] =
                *(const float4*)(Vg + (size_t)d * 2048 + j0 + c4 * 4);
        }
        __syncthreads();

        // ---- MMA1: scores 16q x 128j ----
        float sa[16][4];
        #pragma unroll
        for (int nb = 0; nb < 16; nb++) {
            sa[nb][0] = 0.f; sa[nb][1] = 0.f; sa[nb][2] = 0.f; sa[nb][3] = 0.f;
            const float* kr = &sm[A_KS + (nb * 8 + g) * KPITCH + 2 * t];
            #pragma unroll
            for (int ks = 0; ks < 8; ks++) {
                uint2 b = *(const uint2*)(kr + ks * 8);
                mma8(sa[nb], qa0[ks].x, qa1[ks].x, qa0[ks].y, qa1[ks].y, b.x, b.y);
            }
        }

        // ---- mask + scale ----
        #pragma unroll
        for (int nb = 0; nb < 16; nb++) {
            int2 mv0 = *(const int2*)(mk0 + j0 + nb * 8 + 2 * t);
            int2 mv1 = *(const int2*)(mk1 + j0 + nb * 8 + 2 * t);
            sa[nb][0] = mv0.x ? sa[nb][0] * SCL : -NEGC;
            sa[nb][1] = mv0.y ? sa[nb][1] * SCL : -NEGC;
            sa[nb][2] = mv1.x ? sa[nb][2] * SCL : -NEGC;
            sa[nb][3] = mv1.y ? sa[nb][3] * SCL : -NEGC;
        }

        // ---- row max (quad reduce) ----
        float mx0 = -CUDART_INF_F, mx1 = -CUDART_INF_F;
        #pragma unroll
        for (int nb = 0; nb < 16; nb++) {
            mx0 = fmaxf(mx0, fmaxf(sa[nb][0], sa[nb][1]));
            mx1 = fmaxf(mx1, fmaxf(sa[nb][2], sa[nb][3]));
        }
        mx0 = fmaxf(mx0, __shfl_xor_sync(0xffffffffu, mx0, 1));
        mx0 = fmaxf(mx0, __shfl_xor_sync(0xffffffffu, mx0, 2));
        mx1 = fmaxf(mx1, __shfl_xor_sync(0xffffffffu, mx1, 1));
        mx1 = fmaxf(mx1, __shfl_xor_sync(0xffffffffu, mx1, 2));

        float nm0 = fmaxf(m0r, mx0), nm1 = fmaxf(m1r, mx1);
        float c0 = __expf(m0r - nm0), c1 = __expf(m1r - nm1);
        m0r = nm0; m1r = nm1;

        // ---- exp (tf32 in place) + sums ----
        float s0 = 0.f, s1 = 0.f;
        #pragma unroll
        for (int nb = 0; nb < 16; nb++) {
            float p0 = __expf(sa[nb][0] - nm0);
            float p1 = __expf(sa[nb][1] - nm0);
            float p2 = __expf(sa[nb][2] - nm1);
            float p3 = __expf(sa[nb][3] - nm1);
            s0 += p0 + p1; s1 += p2 + p3;
            sa[nb][0] = __uint_as_float(tf32u(p0));
            sa[nb][1] = __uint_as_float(tf32u(p1));
            sa[nb][2] = __uint_as_float(tf32u(p2));
            sa[nb][3] = __uint_as_float(tf32u(p3));
        }
        s0 += __shfl_xor_sync(0xffffffffu, s0, 1);
        s0 += __shfl_xor_sync(0xffffffffu, s0, 2);
        s1 += __shfl_xor_sync(0xffffffffu, s1, 1);
        s1 += __shfl_xor_sync(0xffffffffu, s1, 2);
        l0r = l0r * c0 + s0;
        l1r = l1r * c1 + s1;

        #pragma unroll
        for (int nd = 0; nd < 8; nd++) {
            o[nd][0] *= c0; o[nd][1] *= c0;
            o[nd][2] *= c1; o[nd][3] *= c1;
        }

        // ---- MMA2: O += P . V (A = score fragments directly) ----
        #pragma unroll
        for (int nd = 0; nd < 8; nd++) {
            const float* vr = &sm[A_VT + (nd * 8 + g) * VPITCH + 2 * t];
            #pragma unroll
            for (int ks = 0; ks < 16; ks++) {
                uint2 b = *(const uint2*)(vr + ks * 8);
                mma8(o[nd],
                     __float_as_uint(sa[ks][0]), __float_as_uint(sa[ks][2]),
                     __float_as_uint(sa[ks][1]), __float_as_uint(sa[ks][3]),
                     b.x, b.y);
            }
        }
    }

    // ---- write split partials ----
    const size_t sr0 = (size_t)sp * (NB * SQ) + (size_t)bb * SQ + row0;
    const size_t sr1 = sr0 + 8;
    #pragma unroll
    for (int nd = 0; nd < 8; nd++) {
        *(float2*)(g_Po + sr0 * 64 + nd * 8 + 2 * t) = make_float2(o[nd][0], o[nd][1]);
        *(float2*)(g_Po + sr1 * 64 + nd * 8 + 2 * t) = make_float2(o[nd][2], o[nd][3]);
    }
    if (t == 0) {
        g_Pm[sr0] = m0r; g_Pl[sr0] = l0r;
        g_Pm[sr1] = m1r; g_Pl[sr1] = l1r;
    }
}

// =======================================================================
// split combine (4 splits)
// =======================================================================
__global__ __launch_bounds__(256) void combine_k(float* __restrict__ out)
{
    int gid = blockIdx.x * 256 + threadIdx.x;
    int row = gid >> 4;
    int c4 = gid & 15;

    float ms[NSPL], ls[NSPL];
    #pragma unroll
    for (int s = 0; s < NSPL; s++) {
        ms[s] = g_Pm[(size_t)s * (NB * SQ) + row];
        ls[s] = g_Pl[(size_t)s * (NB * SQ) + row];
    }
    float m = ms[0];
    #pragma unroll
    for (int s = 1; s < NSPL; s++) m = fmaxf(m, ms[s]);
    float ws[NSPL], denom = 0.f;
    #pragma unroll
    for (int s = 0; s < NSPL; s++) {
        ws[s] = __expf(ms[s] - m);
        denom += ws[s] * ls[s];
    }
    float inv = 1.0f / denom;

    float4 r = make_float4(0.f, 0.f, 0.f, 0.f);
    #pragma unroll
    for (int s = 0; s < NSPL; s++) {
        float4 os = *(const float4*)(g_Po + ((size_t)s * (NB * SQ) + row) * 64 + c4 * 4);
        float wn = ws[s] * inv;
        r.x += os.x * wn; r.y += os.y * wn;
        r.z += os.z * wn; r.w += os.w * wn;
    }
    *(float4*)(out + (size_t)row * 64 + c4 * 4) = r;
}

// ---------------- launch ----------------
extern "C" void kernel_launch(void* const* d_in, const int* in_sizes, int n_in,
                              void* d_out, int out_size)
{
    const float* Q    = (const float*)d_in[0];
    const float* K    = (const float*)d_in[1];
    const float* V    = (const float*)d_in[2];
    const int*   mask = (const int*)  d_in[3];
    const float* Wq   = (const float*)d_in[4];
    const float* bq   = (const float*)d_in[5];
    const float* Wk   = (const float*)d_in[6];
    const float* bk   = (const float*)d_in[7];
    const float* Wv   = (const float*)d_in[8];
    const float* bv   = (const float*)d_in[9];
    float* out = (float*)d_out;

    (void)in_sizes; (void)n_in; (void)out_size;

    const int proj_smem = PROJ_SMEM_FLOATS * 4;   // 58368
    const int att_smem  = ATT_SMEM_FLOATS * 4;    // 71680
    cudaFuncSetAttribute(proj_tc, cudaFuncAttributeMaxDynamicSharedMemorySize, proj_smem);
    cudaFuncSetAttribute(attn_tc, cudaFuncAttributeMaxDynamicSharedMemorySize, att_smem);

    wprep<<<96, 256>>>(Wq, Wk, Wv);
    proj_tc<<<dim3(128, 3), 128, proj_smem>>>(Q, bq, K, bk, V, bv);
    attn_tc<<<dim3(32, NSPL, NB), 128, att_smem>>>(mask);
    combine_k<<<(NB * SQ * 16) / 256, 256>>>(out);
}

// round 14
// speedup vs baseline: 1.6766x; 1.6766x over previous
#include <cuda_runtime.h>
#include <math_constants.h>
#include <cstdint>

#define NB    4
#define SQ    2048
#define UU    1024
#define DKD   64
#define NEGC  1.0e9f
#define SCL   0.125f   // 1/sqrt(64)
#define NSPL  2        // key splits

// ---------------- scratch (no allocation allowed) ----------------
// g_Qp / g_Kp: [8192][64] tf32-rounded, k-dim PERMUTED within 8-groups:
//   group positions hold {k0,k4,k1,k5,k2,k6,k3,k7}
// g_Vt: [B][64(d)][2048(s)] tf32-rounded, transposed
// g_Wp: [3][64][1024] tf32-rounded + permuted weights
__device__ float g_Qp[(size_t)NB * SQ * DKD];
__device__ float g_Kp[(size_t)NB * SQ * DKD];
__device__ float g_Vt[(size_t)NB * DKD * SQ];
__device__ float g_Wp[(size_t)3 * DKD * UU];
// split-K partials
__device__ float g_Po[(size_t)NSPL * NB * SQ * DKD];
__device__ float g_Pm[(size_t)NSPL * NB * SQ];
__device__ float g_Pl[(size_t)NSPL * NB * SQ];

// ---------------- helpers ----------------
__device__ __forceinline__ float tf32f(float x) {
    uint32_t u;
    asm("cvt.rna.tf32.f32 %0, %1;" : "=r"(u) : "f"(x));
    return __uint_as_float(u);
}
__device__ __forceinline__ uint32_t tf32u(float x) {
    uint32_t u;
    asm("cvt.rna.tf32.f32 %0, %1;" : "=r"(u) : "f"(x));
    return u;
}
__device__ __forceinline__ void mma8(float* c,
                                     uint32_t a0, uint32_t a1, uint32_t a2, uint32_t a3,
                                     uint32_t b0, uint32_t b1) {
    asm volatile(
        "mma.sync.aligned.m16n8k8.row.col.f32.tf32.tf32.f32 "
        "{%0,%1,%2,%3}, {%4,%5,%6,%7}, {%8,%9}, {%0,%1,%2,%3};\n"
        : "+f"(c[0]), "+f"(c[1]), "+f"(c[2]), "+f"(c[3])
        : "r"(a0), "r"(a1), "r"(a2), "r"(a3), "r"(b0), "r"(b1));
}
__device__ __forceinline__ uint32_t smem_u32(const void* p) {
    uint32_t a;
    asm("{ .reg .u64 t; cvta.to.shared.u64 t, %1; cvt.u32.u64 %0, t; }" : "=r"(a) : "l"(p));
    return a;
}
#define CP16(dst, src) \
    asm volatile("cp.async.cg.shared.global [%0], [%1], 16;\n" :: "r"(dst), "l"(src))
#define CPCOMMIT() asm volatile("cp.async.commit_group;\n" ::: "memory")
#define CPWAIT(n)  asm volatile("cp.async.wait_group %0;\n" :: "n"(n) : "memory")

// =======================================================================
// W prep: tf32-round + k-permute all three weight matrices into g_Wp.
// =======================================================================
__global__ __launch_bounds__(256) void wprep(
    const float* __restrict__ Wq, const float* __restrict__ Wk, const float* __restrict__ Wv)
{
    int gid = blockIdx.x * 256 + threadIdx.x;   // 0..24575
    int which = gid >> 13;
    int rem = gid & 8191;
    const float* W = (which == 0) ? Wq : (which == 1) ? Wk : Wv;
    const float* src = W + (size_t)rem * 8;
    float4 lo = *(const float4*)(src);
    float4 hi = *(const float4*)(src + 4);
    float* dst = g_Wp + (size_t)which * (DKD * UU) + (size_t)rem * 8;
    *(uint4*)(dst)     = make_uint4(tf32u(lo.x), tf32u(hi.x), tf32u(lo.y), tf32u(hi.y));
    *(uint4*)(dst + 4) = make_uint4(tf32u(lo.z), tf32u(hi.z), tf32u(lo.w), tf32u(hi.w));
}

// =======================================================================
// Projection GEMM: cp.async 3-stage pipeline, k-steps of 32.
// CTA: 64 rows x 64 cols, 128 threads (4 warps x 16 rows). grid (128, 3).
// 3 stages (58.4 KB) -> 3 CTAs/SM -> single wave. (round-12 proven)
// =======================================================================
#define PXPIT 36
#define PWPIT 40
#define PWOFF (64 * PXPIT)                       // 2304
#define PST   (64 * PXPIT + 64 * PWPIT)          // 4864 floats / stage
#define PSTAGES 3
#define PROJ_SMEM_FLOATS (PSTAGES * PST)         // 14592 floats = 58368 B

__global__ __launch_bounds__(128, 3) void proj_tc(
    const float* __restrict__ Qx, const float* __restrict__ bq,
    const float* __restrict__ Kx, const float* __restrict__ bk,
    const float* __restrict__ Vx, const float* __restrict__ bv)
{
    extern __shared__ float sm[];
    const uint32_t sb = smem_u32(sm);

    const int which = blockIdx.y;
    const float* X    = (which == 0) ? Qx : (which == 1) ? Kx : Vx;
    const float* bias = (which == 0) ? bq : (which == 1) ? bk : bv;
    const float* Wp   = g_Wp + (size_t)which * (DKD * UU);

    const int tid = threadIdx.x;
    const int w   = tid >> 5;
    const int lane = tid & 31;
    const int g = lane >> 2;
    const int t = lane & 3;
    const int m0 = blockIdx.x * 64;

    auto issue = [&](int s) {
        const int k0 = s * 32;
        const uint32_t bs = sb + (uint32_t)((s % PSTAGES) * PST) * 4;
        #pragma unroll
        for (int i = 0; i < 4; i++) {
            int idx = tid + i * 128;
            int r = idx >> 3, seg = idx & 7;
            CP16(bs + (uint32_t)(r * PXPIT + seg * 4) * 4,
                 X + (size_t)(m0 + r) * UU + k0 + seg * 4);
        }
        #pragma unroll
        for (int i = 0; i < 4; i++) {
            int idx = tid + i * 128;
            int r = idx >> 3, seg = idx & 7;
            CP16(bs + (uint32_t)(PWOFF + r * PWPIT + seg * 4) * 4,
                 Wp + (size_t)r * UU + k0 + seg * 4);
        }
        CPCOMMIT();
    };

    issue(0); issue(1);

    float acc[8][4] = {};

    for (int kc = 0; kc < 32; kc++) {
        if (kc + 2 < 32) { issue(kc + 2); CPWAIT(2); }
        else             { CPWAIT(0); }
        __syncthreads();

        const float* bX = sm + (kc % PSTAGES) * PST;
        const float* bW = bX + PWOFF;
        const float* xr0 = &bX[(w * 16 + g) * PXPIT + t];
        const float* xr1 = &bX[(w * 16 + 8 + g) * PXPIT + t];

        #pragma unroll
        for (int ks = 0; ks < 4; ks++) {
            const int cb = ks * 8;
            uint32_t a0 = tf32u(xr0[cb]);
            uint32_t a1 = tf32u(xr1[cb]);
            uint32_t a2 = tf32u(xr0[cb + 4]);
            uint32_t a3 = tf32u(xr1[cb + 4]);
            #pragma unroll
            for (int nb = 0; nb < 8; nb++) {
                uint2 b = *(const uint2*)&bW[(nb * 8 + g) * PWPIT + cb + 2 * t];
                mma8(acc[nb], a0, a1, a2, a3, b.x, b.y);
            }
        }
        __syncthreads();
    }

    // epilogue
    const int lr0 = w * 16 + g, lr1 = lr0 + 8;
    const int t2 = 2 * t;
    const int pA = (t2 < 4) ? 2 * t2 : 2 * (t2 - 4) + 1;
    const int pB = (t2 + 1 < 4) ? 2 * (t2 + 1) : 2 * (t2 - 3) + 1;

    if (which < 2) {
        float* dst = (which == 0) ? g_Qp : g_Kp;
        #pragma unroll
        for (int nb = 0; nb < 8; nb++) {
            float b0 = bias[nb * 8 + t2], b1 = bias[nb * 8 + t2 + 1];
            dst[(size_t)(m0 + lr0) * 64 + nb * 8 + pA] = tf32f(acc[nb][0] + b0);
            dst[(size_t)(m0 + lr0) * 64 + nb * 8 + pB] = tf32f(acc[nb][1] + b1);
            dst[(size_t)(m0 + lr1) * 64 + nb * 8 + pA] = tf32f(acc[nb][2] + b0);
            dst[(size_t)(m0 + lr1) * 64 + nb * 8 + pB] = tf32f(acc[nb][3] + b1);
        }
    } else {
        // V: transpose through smem -> g_Vt[b][d][s]
        float* ob = sm;   // [64][68], fits in stage region
        #pragma unroll
        for (int nb = 0; nb < 8; nb++) {
            float b0 = bias[nb * 8 + t2], b1 = bias[nb * 8 + t2 + 1];
            ob[lr0 * 68 + nb * 8 + t2]     = tf32f(acc[nb][0] + b0);
            ob[lr0 * 68 + nb * 8 + t2 + 1] = tf32f(acc[nb][1] + b1);
            ob[lr1 * 68 + nb * 8 + t2]     = tf32f(acc[nb][2] + b0);
            ob[lr1 * 68 + nb * 8 + t2 + 1] = tf32f(acc[nb][3] + b1);
        }
        __syncthreads();
        const int bidx = m0 >> 11;
        const int sbase = m0 & 2047;
        #pragma unroll
        for (int i = 0; i < 8; i++) {
            int idx = tid + i * 128;       // 64 d * 16 s-groups
            int d = idx >> 4, mg = idx & 15;
            float4 v;
            v.x = ob[(mg * 4 + 0) * 68 + d];
            v.y = ob[(mg * 4 + 1) * 68 + d];
            v.z = ob[(mg * 4 + 2) * 68 + d];
            v.w = ob[(mg * 4 + 3) * 68 + d];
            *(float4*)(g_Vt + ((size_t)(bidx * 64 + d)) * 2048 + sbase + mg * 4) = v;
        }
    }
}

// =======================================================================
// Flash attention, split-K (round-12 base + early mask hoist).
// CTA = 4 warps x 16 full query rows, 1024 keys/split, 8 tiles of 128.
// grid (32 q-tiles, 2 splits, 4 batches) = 256 CTAs, 2 CTAs/SM.
// =======================================================================
#define QPITCH 72
#define KPITCH 72
#define VPITCH 136
#define A_QS   0
#define A_KS   (64 * QPITCH)                 // 4608
#define A_VT   (A_KS + 128 * KPITCH)         // 13824
#define ATT_SMEM_FLOATS (A_VT + 64 * VPITCH) // 22528 floats = 90112 B

__global__ __launch_bounds__(128, 2) void attn_tc(
    const int* __restrict__ mask)
{
    extern __shared__ float sm[];
    const int tid = threadIdx.x;
    const int w = tid >> 5;
    const int lane = tid & 31;
    const int g = lane >> 2;
    const int t = lane & 3;
    const int qt = blockIdx.x;
    const int sp = blockIdx.y;
    const int bb = blockIdx.z;
    const int q0 = qt * 64;
    const int kbase = sp * (SQ / NSPL);

    // stage Q tile (already tf32 + permuted)
    const float* Qg = g_Qp + ((size_t)(bb * SQ + q0)) * 64;
    #pragma unroll
    for (int i = 0; i < 8; i++) {
        int idx = tid + i * 128;
        int r = idx >> 4, c4 = idx & 15;
        *(float4*)&sm[A_QS + r * QPITCH + c4 * 4] =
            *(const float4*)(Qg + (size_t)r * 64 + c4 * 4);
    }
    __syncthreads();

    uint2 qa0[8], qa1[8];
    {
        const float* r0p = &sm[A_QS + (w * 16 + g) * QPITCH + 2 * t];
        const float* r1p = &sm[A_QS + (w * 16 + 8 + g) * QPITCH + 2 * t];
        #pragma unroll
        for (int ks = 0; ks < 8; ks++) {
            qa0[ks] = *(const uint2*)(r0p + ks * 8);
            qa1[ks] = *(const uint2*)(r1p + ks * 8);
        }
    }

    float m0r = -CUDART_INF_F, m1r = -CUDART_INF_F;
    float l0r = 0.f, l1r = 0.f;
    float o[8][4] = {};

    const int row0 = q0 + w * 16 + g, row1 = row0 + 8;
    const int* mk0 = mask + ((size_t)(bb * SQ + row0)) * SQ + kbase;
    const int* mk1 = mask + ((size_t)(bb * SQ + row1)) * SQ + kbase;
    const float* Kg = g_Kp + ((size_t)(bb * SQ + kbase)) * 64;
    const float* Vg = g_Vt + ((size_t)bb * 64) * 2048 + kbase;

    for (int tile = 0; tile < (SQ / NSPL) / 128; tile++) {
        const int j0 = tile * 128;

        __syncthreads();
        // stage K tile (straight copy, perm layout)
        #pragma unroll
        for (int i = 0; i < 16; i++) {
            int idx = tid + i * 128;
            int r = idx >> 4, c4 = idx & 15;
            *(float4*)&sm[A_KS + r * KPITCH + c4 * 4] =
                *(const float4*)(Kg + (size_t)(j0 + r) * 64 + c4 * 4);
        }
        // stage V^T tile
        #pragma unroll
        for (int i = 0; i < 16; i++) {
            int idx = tid + i * 128;
            int d = idx >> 5, c4 = idx & 31;
            *(float4*)&sm[A_VT + d * VPITCH + c4 * 4] =
                *(const float4*)(Vg + (size_t)d * 2048 + j0 + c4 * 4);
        }

        // ---- mask loads hoisted here: their ~600cyc latency overlaps the
        //      staging sync + MMA1 instead of serializing after MMA1 ----
        int2 pm0[16], pm1[16];
        #pragma unroll
        for (int nb = 0; nb < 16; nb++) {
            pm0[nb] = *(const int2*)(mk0 + j0 + nb * 8 + 2 * t);
            pm1[nb] = *(const int2*)(mk1 + j0 + nb * 8 + 2 * t);
        }
        __syncthreads();

        // ---- MMA1: scores 16q x 128j ----
        float sa[16][4];
        #pragma unroll
        for (int nb = 0; nb < 16; nb++) {
            sa[nb][0] = 0.f; sa[nb][1] = 0.f; sa[nb][2] = 0.f; sa[nb][3] = 0.f;
            const float* kr = &sm[A_KS + (nb * 8 + g) * KPITCH + 2 * t];
            #pragma unroll
            for (int ks = 0; ks < 8; ks++) {
                uint2 b = *(const uint2*)(kr + ks * 8);
                mma8(sa[nb], qa0[ks].x, qa1[ks].x, qa0[ks].y, qa1[ks].y, b.x, b.y);
            }
        }

        // ---- mask + scale (registers, no LDG here) ----
        #pragma unroll
        for (int nb = 0; nb < 16; nb++) {
            sa[nb][0] = pm0[nb].x ? sa[nb][0] * SCL : -NEGC;
            sa[nb][1] = pm0[nb].y ? sa[nb][1] * SCL : -NEGC;
            sa[nb][2] = pm1[nb].x ? sa[nb][2] * SCL : -NEGC;
            sa[nb][3] = pm1[nb].y ? sa[nb][3] * SCL : -NEGC;
        }

        // ---- row max (quad reduce) ----
        float mx0 = -CUDART_INF_F, mx1 = -CUDART_INF_F;
        #pragma unroll
        for (int nb = 0; nb < 16; nb++) {
            mx0 = fmaxf(mx0, fmaxf(sa[nb][0], sa[nb][1]));
            mx1 = fmaxf(mx1, fmaxf(sa[nb][2], sa[nb][3]));
        }
        mx0 = fmaxf(mx0, __shfl_xor_sync(0xffffffffu, mx0, 1));
        mx0 = fmaxf(mx0, __shfl_xor_sync(0xffffffffu, mx0, 2));
        mx1 = fmaxf(mx1, __shfl_xor_sync(0xffffffffu, mx1, 1));
        mx1 = fmaxf(mx1, __shfl_xor_sync(0xffffffffu, mx1, 2));

        float nm0 = fmaxf(m0r, mx0), nm1 = fmaxf(m1r, mx1);
        float c0 = __expf(m0r - nm0), c1 = __expf(m1r - nm1);
        m0r = nm0; m1r = nm1;

        // ---- exp (tf32 in place) + sums ----
        float s0 = 0.f, s1 = 0.f;
        #pragma unroll
        for (int nb = 0; nb < 16; nb++) {
            float p0 = __expf(sa[nb][0] - nm0);
            float p1 = __expf(sa[nb][1] - nm0);
            float p2 = __expf(sa[nb][2] - nm1);
            float p3 = __expf(sa[nb][3] - nm1);
            s0 += p0 + p1; s1 += p2 + p3;
            sa[nb][0] = __uint_as_float(tf32u(p0));
            sa[nb][1] = __uint_as_float(tf32u(p1));
            sa[nb][2] = __uint_as_float(tf32u(p2));
            sa[nb][3] = __uint_as_float(tf32u(p3));
        }
        s0 += __shfl_xor_sync(0xffffffffu, s0, 1);
        s0 += __shfl_xor_sync(0xffffffffu, s0, 2);
        s1 += __shfl_xor_sync(0xffffffffu, s1, 1);
        s1 += __shfl_xor_sync(0xffffffffu, s1, 2);
        l0r = l0r * c0 + s0;
        l1r = l1r * c1 + s1;

        #pragma unroll
        for (int nd = 0; nd < 8; nd++) {
            o[nd][0] *= c0; o[nd][1] *= c0;
            o[nd][2] *= c1; o[nd][3] *= c1;
        }

        // ---- MMA2: O += P . V (A = score fragments directly) ----
        #pragma unroll
        for (int nd = 0; nd < 8; nd++) {
            const float* vr = &sm[A_VT + (nd * 8 + g) * VPITCH + 2 * t];
            #pragma unroll
            for (int ks = 0; ks < 16; ks++) {
                uint2 b = *(const uint2*)(vr + ks * 8);
                mma8(o[nd],
                     __float_as_uint(sa[ks][0]), __float_as_uint(sa[ks][2]),
                     __float_as_uint(sa[ks][1]), __float_as_uint(sa[ks][3]),
                     b.x, b.y);
            }
        }
    }

    // ---- write split partials ----
    const size_t sr0 = (size_t)sp * (NB * SQ) + (size_t)bb * SQ + row0;
    const size_t sr1 = sr0 + 8;
    #pragma unroll
    for (int nd = 0; nd < 8; nd++) {
        *(float2*)(g_Po + sr0 * 64 + nd * 8 + 2 * t) = make_float2(o[nd][0], o[nd][1]);
        *(float2*)(g_Po + sr1 * 64 + nd * 8 + 2 * t) = make_float2(o[nd][2], o[nd][3]);
    }
    if (t == 0) {
        g_Pm[sr0] = m0r; g_Pl[sr0] = l0r;
        g_Pm[sr1] = m1r; g_Pl[sr1] = l1r;
    }
}

// =======================================================================
// split combine (round-12 proven version)
// =======================================================================
__global__ __launch_bounds__(256) void combine_k(float* __restrict__ out)
{
    int gid = blockIdx.x * 256 + threadIdx.x;
    int row = gid >> 4;
    int c4 = gid & 15;
    float m1 = g_Pm[row], m2 = g_Pm[NB * SQ + row];
    float l1 = g_Pl[row], l2 = g_Pl[NB * SQ + row];
    float m = fmaxf(m1, m2);
    float w1 = __expf(m1 - m), w2 = __expf(m2 - m);
    float inv = 1.0f / (w1 * l1 + w2 * l2);
    w1 *= inv; w2 *= inv;
    float4 o1 = *(const float4*)(g_Po + (size_t)row * 64 + c4 * 4);
    float4 o2 = *(const float4*)(g_Po + ((size_t)(NB * SQ + row)) * 64 + c4 * 4);
    float4 r;
    r.x = o1.x * w1 + o2.x * w2;
    r.y = o1.y * w1 + o2.y * w2;
    r.z = o1.z * w1 + o2.z * w2;
    r.w = o1.w * w1 + o2.w * w2;
    *(float4*)(out + (size_t)row * 64 + c4 * 4) = r;
}

// ---------------- launch ----------------
extern "C" void kernel_launch(void* const* d_in, const int* in_sizes, int n_in,
                              void* d_out, int out_size)
{
    const float* Q    = (const float*)d_in[0];
    const float* K    = (const float*)d_in[1];
    const float* V    = (const float*)d_in[2];
    const int*   mask = (const int*)  d_in[3];
    const float* Wq   = (const float*)d_in[4];
    const float* bq   = (const float*)d_in[5];
    const float* Wk   = (const float*)d_in[6];
    const float* bk   = (const float*)d_in[7];
    const float* Wv   = (const float*)d_in[8];
    const float* bv   = (const float*)d_in[9];
    float* out = (float*)d_out;

    (void)in_sizes; (void)n_in; (void)out_size;

    const int proj_smem = PROJ_SMEM_FLOATS * 4;   // 58368
    const int att_smem  = ATT_SMEM_FLOATS * 4;    // 90112
    cudaFuncSetAttribute(proj_tc, cudaFuncAttributeMaxDynamicSharedMemorySize, proj_smem);
    cudaFuncSetAttribute(attn_tc, cudaFuncAttributeMaxDynamicSharedMemorySize, att_smem);

    wprep<<<96, 256>>>(Wq, Wk, Wv);
    proj_tc<<<dim3(128, 3), 128, proj_smem>>>(Q, bq, K, bk, V, bv);
    attn_tc<<<dim3(32, NSPL, NB), 128, att_smem>>>(mask);
    combine_k<<<(NB * SQ * 16) / 256, 256>>>(out);
}

// round 15
// speedup vs baseline: 2.1025x; 1.2540x over previous
#include <cuda_runtime.h>
#include <cuda_fp16.h>
#include <math_constants.h>
#include <cstdint>

#define NB    4
#define SQ    2048
#define UU    1024
#define DKD   64
#define NEGC  1.0e9f
#define SCL   0.125f   // 1/sqrt(64)
#define NSPL  2        // key splits

// ---------------- scratch (no allocation allowed) ----------------
// g_Qh / g_Kh: [8192][64] fp16, d-dim PAIR-PERMUTED per 16-group:
//   pos 4j..4j+3 hold d = {2j, 2j+1, 2j+8, 2j+9}  (j=0..3 within group)
// g_Vth: [B][64(d)][2048(s)] fp16, transposed, s pair-permuted per 16-group
// g_Wp: [3][64][1024] tf32-rounded + permuted weights (proj B operand)
__device__ __half g_Qh[(size_t)NB * SQ * DKD];
__device__ __half g_Kh[(size_t)NB * SQ * DKD];
__device__ __half g_Vth[(size_t)NB * DKD * SQ];
__device__ float  g_Wp[(size_t)3 * DKD * UU];
// split-K partials
__device__ float g_Po[(size_t)NSPL * NB * SQ * DKD];
__device__ float g_Pm[(size_t)NSPL * NB * SQ];
__device__ float g_Pl[(size_t)NSPL * NB * SQ];

// ---------------- helpers ----------------
__device__ __forceinline__ uint32_t tf32u(float x) {
    uint32_t u;
    asm("cvt.rna.tf32.f32 %0, %1;" : "=r"(u) : "f"(x));
    return u;
}
__device__ __forceinline__ uint32_t packh2(float lo, float hi) {
    __half2 h = __floats2half2_rn(lo, hi);   // .x (low) = lo
    return reinterpret_cast<uint32_t&>(h);
}
// tf32 m16n8k8 (projection)
__device__ __forceinline__ void mma8(float* c,
                                     uint32_t a0, uint32_t a1, uint32_t a2, uint32_t a3,
                                     uint32_t b0, uint32_t b1) {
    asm volatile(
        "mma.sync.aligned.m16n8k8.row.col.f32.tf32.tf32.f32 "
        "{%0,%1,%2,%3}, {%4,%5,%6,%7}, {%8,%9}, {%0,%1,%2,%3};\n"
        : "+f"(c[0]), "+f"(c[1]), "+f"(c[2]), "+f"(c[3])
        : "r"(a0), "r"(a1), "r"(a2), "r"(a3), "r"(b0), "r"(b1));
}
// fp16 m16n8k16, f32 accum (attention)
__device__ __forceinline__ void mma16h(float* c,
                                       uint32_t a0, uint32_t a1, uint32_t a2, uint32_t a3,
                                       uint32_t b0, uint32_t b1) {
    asm volatile(
        "mma.sync.aligned.m16n8k16.row.col.f32.f16.f16.f32 "
        "{%0,%1,%2,%3}, {%4,%5,%6,%7}, {%8,%9}, {%0,%1,%2,%3};\n"
        : "+f"(c[0]), "+f"(c[1]), "+f"(c[2]), "+f"(c[3])
        : "r"(a0), "r"(a1), "r"(a2), "r"(a3), "r"(b0), "r"(b1));
}
__device__ __forceinline__ uint32_t smem_u32(const void* p) {
    uint32_t a;
    asm("{ .reg .u64 t; cvta.to.shared.u64 t, %1; cvt.u32.u64 %0, t; }" : "=r"(a) : "l"(p));
    return a;
}
#define CP16(dst, src) \
    asm volatile("cp.async.cg.shared.global [%0], [%1], 16;\n" :: "r"(dst), "l"(src))
#define CPCOMMIT() asm volatile("cp.async.commit_group;\n" ::: "memory")
#define CPWAIT(n)  asm volatile("cp.async.wait_group %0;\n" :: "n"(n) : "memory")

// =======================================================================
// W prep (unchanged): tf32-round + k-permute weights into g_Wp.
// =======================================================================
__global__ __launch_bounds__(256) void wprep(
    const float* __restrict__ Wq, const float* __restrict__ Wk, const float* __restrict__ Wv)
{
    int gid = blockIdx.x * 256 + threadIdx.x;   // 0..24575
    int which = gid >> 13;
    int rem = gid & 8191;
    const float* W = (which == 0) ? Wq : (which == 1) ? Wk : Wv;
    const float* src = W + (size_t)rem * 8;
    float4 lo = *(const float4*)(src);
    float4 hi = *(const float4*)(src + 4);
    float* dst = g_Wp + (size_t)which * (DKD * UU) + (size_t)rem * 8;
    *(uint4*)(dst)     = make_uint4(tf32u(lo.x), tf32u(hi.x), tf32u(lo.y), tf32u(hi.y));
    *(uint4*)(dst + 4) = make_uint4(tf32u(lo.z), tf32u(hi.z), tf32u(lo.w), tf32u(hi.w));
}

// =======================================================================
// Projection GEMM (round-12 proven core): cp.async 3-stage, k-steps 32.
// Epilogue now emits fp16 permuted Q/K and fp16 permuted V^T.
// =======================================================================
#define PXPIT 36
#define PWPIT 40
#define PWOFF (64 * PXPIT)                       // 2304
#define PST   (64 * PXPIT + 64 * PWPIT)          // 4864 floats / stage
#define PSTAGES 3
#define PROJ_SMEM_FLOATS (PSTAGES * PST)         // 58368 B

__global__ __launch_bounds__(128, 3) void proj_tc(
    const float* __restrict__ Qx, const float* __restrict__ bq,
    const float* __restrict__ Kx, const float* __restrict__ bk,
    const float* __restrict__ Vx, const float* __restrict__ bv)
{
    extern __shared__ float sm[];
    const uint32_t sb = smem_u32(sm);

    const int which = blockIdx.y;
    const float* X    = (which == 0) ? Qx : (which == 1) ? Kx : Vx;
    const float* bias = (which == 0) ? bq : (which == 1) ? bk : bv;
    const float* Wp   = g_Wp + (size_t)which * (DKD * UU);

    const int tid = threadIdx.x;
    const int w   = tid >> 5;
    const int lane = tid & 31;
    const int g = lane >> 2;
    const int t = lane & 3;
    const int m0 = blockIdx.x * 64;

    auto issue = [&](int s) {
        const int k0 = s * 32;
        const uint32_t bs = sb + (uint32_t)((s % PSTAGES) * PST) * 4;
        #pragma unroll
        for (int i = 0; i < 4; i++) {
            int idx = tid + i * 128;
            int r = idx >> 3, seg = idx & 7;
            CP16(bs + (uint32_t)(r * PXPIT + seg * 4) * 4,
                 X + (size_t)(m0 + r) * UU + k0 + seg * 4);
        }
        #pragma unroll
        for (int i = 0; i < 4; i++) {
            int idx = tid + i * 128;
            int r = idx >> 3, seg = idx & 7;
            CP16(bs + (uint32_t)(PWOFF + r * PWPIT + seg * 4) * 4,
                 Wp + (size_t)r * UU + k0 + seg * 4);
        }
        CPCOMMIT();
    };

    issue(0); issue(1);

    float acc[8][4] = {};

    for (int kc = 0; kc < 32; kc++) {
        if (kc + 2 < 32) { issue(kc + 2); CPWAIT(2); }
        else             { CPWAIT(0); }
        __syncthreads();

        const float* bX = sm + (kc % PSTAGES) * PST;
        const float* bW = bX + PWOFF;
        const float* xr0 = &bX[(w * 16 + g) * PXPIT + t];
        const float* xr1 = &bX[(w * 16 + 8 + g) * PXPIT + t];

        #pragma unroll
        for (int ks = 0; ks < 4; ks++) {
            const int cb = ks * 8;
            uint32_t a0 = tf32u(xr0[cb]);
            uint32_t a1 = tf32u(xr1[cb]);
            uint32_t a2 = tf32u(xr0[cb + 4]);
            uint32_t a3 = tf32u(xr1[cb + 4]);
            #pragma unroll
            for (int nb = 0; nb < 8; nb++) {
                uint2 b = *(const uint2*)&bW[(nb * 8 + g) * PWPIT + cb + 2 * t];
                mma8(acc[nb], a0, a1, a2, a3, b.x, b.y);
            }
        }
        __syncthreads();
    }

    // epilogue
    const int lr0 = w * 16 + g, lr1 = lr0 + 8;
    const int t2 = 2 * t;

    if (which < 2) {
        // Q/K -> fp16, pair-permuted per 16-group:
        // col c = nb*8 + 2t  ->  pos = 16*(nb>>1) + 2*(nb&1) + 4*t  (pair c,c+1 contiguous)
        __half* dst = (which == 0) ? g_Qh : g_Kh;
        #pragma unroll
        for (int nb = 0; nb < 8; nb++) {
            float b0 = bias[nb * 8 + t2], b1 = bias[nb * 8 + t2 + 1];
            int pos = 16 * (nb >> 1) + 2 * (nb & 1) + 4 * t;
            uint32_t h0 = packh2(acc[nb][0] + b0, acc[nb][1] + b1);
            uint32_t h1 = packh2(acc[nb][2] + b0, acc[nb][3] + b1);
            *(uint32_t*)(dst + (size_t)(m0 + lr0) * 64 + pos) = h0;
            *(uint32_t*)(dst + (size_t)(m0 + lr1) * 64 + pos) = h1;
        }
    } else {
        // V: fp32 transpose through smem, then fp16 permuted store to g_Vth[b][d][s]
        float* ob = sm;   // [64][68]
        #pragma unroll
        for (int nb = 0; nb < 8; nb++) {
            float b0 = bias[nb * 8 + t2], b1 = bias[nb * 8 + t2 + 1];
            ob[lr0 * 68 + nb * 8 + t2]     = acc[nb][0] + b0;
            ob[lr0 * 68 + nb * 8 + t2 + 1] = acc[nb][1] + b1;
            ob[lr1 * 68 + nb * 8 + t2]     = acc[nb][2] + b0;
            ob[lr1 * 68 + nb * 8 + t2 + 1] = acc[nb][3] + b1;
        }
        __syncthreads();
        const int bidx = m0 >> 11;
        const int sbase = m0 & 2047;
        #pragma unroll
        for (int i = 0; i < 8; i++) {
            int idx = tid + i * 128;       // 64 d * 16 s-groups of 4
            int d = idx >> 4, mg = idx & 15;
            float v0 = ob[(mg * 4 + 0) * 68 + d];
            float v1 = ob[(mg * 4 + 1) * 68 + d];
            float v2 = ob[(mg * 4 + 2) * 68 + d];
            float v3 = ob[(mg * 4 + 3) * 68 + d];
            // s pair-permutation within 16-group: a = mg&3,
            // pair0 -> p0 = (a&1)*8 + (a>>1)*2, pair1 -> p0+4
            int a = mg & 3;
            int grp = (sbase >> 4) + (mg >> 2);
            int p0 = (a & 1) * 8 + (a >> 1) * 2;
            __half* vrow = g_Vth + ((size_t)(bidx * 64 + d)) * 2048 + grp * 16;
            *(uint32_t*)(vrow + p0)     = packh2(v0, v1);
            *(uint32_t*)(vrow + p0 + 4) = packh2(v2, v3);
        }
    }
}

// =======================================================================
// Flash attention, split-K, fp16 m16n8k16.
// CTA = 4 warps x 16 full query rows, 1024 keys/split, 8 tiles of 128.
// grid (32, 2, 4) = 256 CTAs, 2 CTAs/SM.
// smem (halves): Q 64x80, K 128x80, Vt 64x144  -> 49152 B total.
// Row strides 80h/144h = 40/72 words (== 8 mod 32) -> conflict-free LDS.64.
// =======================================================================
#define H_QS   0
#define H_KS   (64 * 80)                  // 5120
#define H_VT   (H_KS + 128 * 80)          // 15360
#define ATT_SMEM_BYTES ((H_VT + 64 * 144) * 2)   // 49152

__global__ __launch_bounds__(128, 2) void attn_tc(
    const int* __restrict__ mask)
{
    extern __shared__ __half smh[];
    const int tid = threadIdx.x;
    const int w = tid >> 5;
    const int lane = tid & 31;
    const int g = lane >> 2;
    const int t = lane & 3;
    const int qt = blockIdx.x;
    const int sp = blockIdx.y;
    const int bb = blockIdx.z;
    const int q0 = qt * 64;
    const int kbase = sp * (SQ / NSPL);

    // stage Q tile (fp16 permuted, straight copy: 64 rows x 128B)
    const __half* Qg = g_Qh + ((size_t)(bb * SQ + q0)) * 64;
    #pragma unroll
    for (int i = 0; i < 4; i++) {
        int idx = tid + i * 128;
        int r = idx >> 3, seg = idx & 7;
        *(float4*)((char*)smh + r * 160 + seg * 16) =
            *(const float4*)(Qg + (size_t)r * 64 + seg * 8);
    }
    __syncthreads();

    // resident Q fragments: uint2 = {a0(row g, d 2t/2t+1 | 2t+8/2t+9 packed)}
    uint2 qa0[4], qa1[4];
    {
        const __half* r0p = smh + H_QS + (w * 16 + g) * 80 + 4 * t;
        const __half* r1p = smh + H_QS + (w * 16 + 8 + g) * 80 + 4 * t;
        #pragma unroll
        for (int ks = 0; ks < 4; ks++) {
            qa0[ks] = *(const uint2*)(r0p + ks * 16);
            qa1[ks] = *(const uint2*)(r1p + ks * 16);
        }
    }

    float m0r = -CUDART_INF_F, m1r = -CUDART_INF_F;
    float l0r = 0.f, l1r = 0.f;
    float o[8][4] = {};

    const int row0 = q0 + w * 16 + g, row1 = row0 + 8;
    const int* mk0 = mask + ((size_t)(bb * SQ + row0)) * SQ + kbase;
    const int* mk1 = mask + ((size_t)(bb * SQ + row1)) * SQ + kbase;
    const __half* Kg = g_Kh + ((size_t)(bb * SQ + kbase)) * 64;
    const __half* Vg = g_Vth + ((size_t)bb * 64) * 2048 + kbase;

    for (int tile = 0; tile < (SQ / NSPL) / 128; tile++) {
        const int j0 = tile * 128;

        __syncthreads();
        // stage K tile: 128 rows x 128B
        #pragma unroll
        for (int i = 0; i < 8; i++) {
            int idx = tid + i * 128;
            int r = idx >> 3, seg = idx & 7;
            *(float4*)((char*)smh + H_KS * 2 + r * 160 + seg * 16) =
                *(const float4*)(Kg + (size_t)(j0 + r) * 64 + seg * 8);
        }
        // stage V^T tile: 64 rows x 256B (s already permuted in gmem)
        #pragma unroll
        for (int i = 0; i < 8; i++) {
            int idx = tid + i * 128;
            int d = idx >> 4, seg = idx & 15;
            *(float4*)((char*)smh + H_VT * 2 + d * 288 + seg * 16) =
                *(const float4*)(Vg + (size_t)d * 2048 + j0 + seg * 8);
        }
        __syncthreads();

        // ---- MMA1: scores 16q x 128j, fp16 K=16 (4 chunks) ----
        float sa[16][4];
        #pragma unroll
        for (int nb = 0; nb < 16; nb++) {
            sa[nb][0] = 0.f; sa[nb][1] = 0.f; sa[nb][2] = 0.f; sa[nb][3] = 0.f;
            const __half* kr = smh + H_KS + (nb * 8 + g) * 80 + 4 * t;
            #pragma unroll
            for (int ks = 0; ks < 4; ks++) {
                uint2 b = *(const uint2*)(kr + ks * 16);
                mma16h(sa[nb], qa0[ks].x, qa1[ks].x, qa0[ks].y, qa1[ks].y, b.x, b.y);
            }
        }

        // ---- mask + scale ----
        #pragma unroll
        for (int nb = 0; nb < 16; nb++) {
            int2 mv0 = *(const int2*)(mk0 + j0 + nb * 8 + 2 * t);
            int2 mv1 = *(const int2*)(mk1 + j0 + nb * 8 + 2 * t);
            sa[nb][0] = mv0.x ? sa[nb][0] * SCL : -NEGC;
            sa[nb][1] = mv0.y ? sa[nb][1] * SCL : -NEGC;
            sa[nb][2] = mv1.x ? sa[nb][2] * SCL : -NEGC;
            sa[nb][3] = mv1.y ? sa[nb][3] * SCL : -NEGC;
        }

        // ---- row max (quad reduce) ----
        float mx0 = -CUDART_INF_F, mx1 = -CUDART_INF_F;
        #pragma unroll
        for (int nb = 0; nb < 16; nb++) {
            mx0 = fmaxf(mx0, fmaxf(sa[nb][0], sa[nb][1]));
            mx1 = fmaxf(mx1, fmaxf(sa[nb][2], sa[nb][3]));
        }
        mx0 = fmaxf(mx0, __shfl_xor_sync(0xffffffffu, mx0, 1));
        mx0 = fmaxf(mx0, __shfl_xor_sync(0xffffffffu, mx0, 2));
        mx1 = fmaxf(mx1, __shfl_xor_sync(0xffffffffu, mx1, 1));
        mx1 = fmaxf(mx1, __shfl_xor_sync(0xffffffffu, mx1, 2));

        float nm0 = fmaxf(m0r, mx0), nm1 = fmaxf(m1r, mx1);
        float c0 = __expf(m0r - nm0), c1 = __expf(m1r - nm1);
        m0r = nm0; m1r = nm1;

        // ---- exp + sums; pack P to fp16x2 (MMA2 A fragments) ----
        uint32_t pt[16][2];
        float s0 = 0.f, s1 = 0.f;
        #pragma unroll
        for (int nb = 0; nb < 16; nb++) {
            float p0 = __expf(sa[nb][0] - nm0);
            float p1 = __expf(sa[nb][1] - nm0);
            float p2 = __expf(sa[nb][2] - nm1);
            float p3 = __expf(sa[nb][3] - nm1);
            s0 += p0 + p1; s1 += p2 + p3;
            pt[nb][0] = packh2(p0, p1);   // row g,   keys (nb*8+2t, +1)
            pt[nb][1] = packh2(p2, p3);   // row g+8
        }
        s0 += __shfl_xor_sync(0xffffffffu, s0, 1);
        s0 += __shfl_xor_sync(0xffffffffu, s0, 2);
        s1 += __shfl_xor_sync(0xffffffffu, s1, 1);
        s1 += __shfl_xor_sync(0xffffffffu, s1, 2);
        l0r = l0r * c0 + s0;
        l1r = l1r * c1 + s1;

        #pragma unroll
        for (int nd = 0; nd < 8; nd++) {
            o[nd][0] *= c0; o[nd][1] *= c0;
            o[nd][2] *= c1; o[nd][3] *= c1;
        }

        // ---- MMA2: O += P . V  (K=16: A = pt pairs of adjacent nb) ----
        #pragma unroll
        for (int nd = 0; nd < 8; nd++) {
            const __half* vr = smh + H_VT + (nd * 8 + g) * 144 + 4 * t;
            #pragma unroll
            for (int ks = 0; ks < 8; ks++) {
                uint2 b = *(const uint2*)(vr + ks * 16);
                mma16h(o[nd],
                       pt[2 * ks][0], pt[2 * ks][1],
                       pt[2 * ks + 1][0], pt[2 * ks + 1][1],
                       b.x, b.y);
            }
        }
    }

    // ---- write split partials ----
    const size_t sr0 = (size_t)sp * (NB * SQ) + (size_t)bb * SQ + row0;
    const size_t sr1 = sr0 + 8;
    #pragma unroll
    for (int nd = 0; nd < 8; nd++) {
        *(float2*)(g_Po + sr0 * 64 + nd * 8 + 2 * t) = make_float2(o[nd][0], o[nd][1]);
        *(float2*)(g_Po + sr1 * 64 + nd * 8 + 2 * t) = make_float2(o[nd][2], o[nd][3]);
    }
    if (t == 0) {
        g_Pm[sr0] = m0r; g_Pl[sr0] = l0r;
        g_Pm[sr1] = m1r; g_Pl[sr1] = l1r;
    }
}

// =======================================================================
// split combine (round-12 proven version)
// =======================================================================
__global__ __launch_bounds__(256) void combine_k(float* __restrict__ out)
{
    int gid = blockIdx.x * 256 + threadIdx.x;
    int row = gid >> 4;
    int c4 = gid & 15;
    float m1 = g_Pm[row], m2 = g_Pm[NB * SQ + row];
    float l1 = g_Pl[row], l2 = g_Pl[NB * SQ + row];
    float m = fmaxf(m1, m2);
    float w1 = __expf(m1 - m), w2 = __expf(m2 - m);
    float inv = 1.0f / (w1 * l1 + w2 * l2);
    w1 *= inv; w2 *= inv;
    float4 o1 = *(const float4*)(g_Po + (size_t)row * 64 + c4 * 4);
    float4 o2 = *(const float4*)(g_Po + ((size_t)(NB * SQ + row)) * 64 + c4 * 4);
    float4 r;
    r.x = o1.x * w1 + o2.x * w2;
    r.y = o1.y * w1 + o2.y * w2;
    r.z = o1.z * w1 + o2.z * w2;
    r.w = o1.w * w1 + o2.w * w2;
    *(float4*)(out + (size_t)row * 64 + c4 * 4) = r;
}

// ---------------- launch ----------------
extern "C" void kernel_launch(void* const* d_in, const int* in_sizes, int n_in,
                              void* d_out, int out_size)
{
    const float* Q    = (const float*)d_in[0];
    const float* K    = (const float*)d_in[1];
    const float* V    = (const float*)d_in[2];
    const int*   mask = (const int*)  d_in[3];
    const float* Wq   = (const float*)d_in[4];
    const float* bq   = (const float*)d_in[5];
    const float* Wk   = (const float*)d_in[6];
    const float* bk   = (const float*)d_in[7];
    const float* Wv   = (const float*)d_in[8];
    const float* bv   = (const float*)d_in[9];
    float* out = (float*)d_out;

    (void)in_sizes; (void)n_in; (void)out_size;

    const int proj_smem = PROJ_SMEM_FLOATS * 4;   // 58368
    const int att_smem  = ATT_SMEM_BYTES;         // 49152
    cudaFuncSetAttribute(proj_tc, cudaFuncAttributeMaxDynamicSharedMemorySize, proj_smem);
    cudaFuncSetAttribute(attn_tc, cudaFuncAttributeMaxDynamicSharedMemorySize, att_smem);

    wprep<<<96, 256>>>(Wq, Wk, Wv);
    proj_tc<<<dim3(128, 3), 128, proj_smem>>>(Q, bq, K, bk, V, bv);
    attn_tc<<<dim3(32, NSPL, NB), 128, att_smem>>>(mask);
    combine_k<<<(NB * SQ * 16) / 256, 256>>>(out);
}